// round 8
// baseline (speedup 1.0000x reference)
#include <cuda_runtime.h>
#include <math.h>

#define NA 192
#define TT 80
#define NC 5
#define THREADS 256
#define NTILE 21            // upper-triangular 32x32 tiles of 192x192
#define PLANE (NC * NA)     // 960 floats per coordinate plane
#define TP 33               // transpose tile pitch (conflict-free)

__constant__ int c_bi[NTILE] = {0,0,0,0,0,0, 1,1,1,1,1, 2,2,2,2, 3,3,3, 4,4, 5};
__constant__ int c_bj[NTILE] = {0,1,2,3,4,5, 1,2,3,4,5, 2,3,4,5, 3,4,5, 4,5, 5};

// packed {-v, -v}
#define PACK_NEG2(dst, v) \
    asm("mov.b64 %0, {%1, %1};" : "=l"(dst) : "f"(-(v)))

// two squared distances (packed f32x2) + scalar running mins on the halves
#define CIRC2(mlo, mhi, xj, nxi, yj, nyi)                         \
    asm("{\n\t"                                                   \
        ".reg .b64 dx, dy, d2;\n\t"                               \
        ".reg .f32 lo, hi;\n\t"                                   \
        "add.rn.f32x2 dx, %2, %3;\n\t"                            \
        "add.rn.f32x2 dy, %4, %5;\n\t"                            \
        "mul.rn.f32x2 d2, dy, dy;\n\t"                            \
        "fma.rn.f32x2 d2, dx, dx, d2;\n\t"                        \
        "mov.b64 {lo, hi}, d2;\n\t"                               \
        "min.f32 %0, %0, lo;\n\t"                                 \
        "min.f32 %1, %1, hi;\n\t"                                 \
        "}"                                                       \
        : "+f"(mlo), "+f"(mhi)                                    \
        : "l"(xj), "l"(nxi), "l"(yj), "l"(nyi))

// ---- single fused kernel: build slab for t in-block, then pair tiles ----
__global__ void __launch_bounds__(THREADS)
veh_kernel(const float* __restrict__ traj,   // (NA, T, 4)
           const float* __restrict__ cent,   // (NA, NC, 4)
           const float* __restrict__ pd,     // (NA, NA)
           float* __restrict__ out)
{
    const int t   = blockIdx.y;
    const int tid = threadIdx.x;

    __shared__ __align__(16) float s[2 * PLANE];     // world x then y  (7.5 KB)
    __shared__ __align__(16) float scc[2 * PLANE];   // cent x then y   (7.5 KB)
    __shared__ float tpen[32 * TP];
    __shared__ float tmsk[32 * TP];
    float* __restrict__ swx = s;
    float* __restrict__ swy = s + PLANE;

    // ---- stage centroids coalesced: (a*NC+c) float4 -> scc[c][a] ----
    {
        const float4* __restrict__ c4 = reinterpret_cast<const float4*>(cent);
        #pragma unroll
        for (int k = tid; k < PLANE; k += THREADS) {
            const float4 v = c4[k];          // stride-1: coalesced
            const int a = k / NC;
            const int c = k - a * NC;
            scc[c * NA + a]         = v.x;
            scc[PLANE + c * NA + a] = v.y;
        }
    }
    __syncthreads();

    // ---- build world circles for all 192 agents at this t ----
    if (tid < NA) {
        const int a = tid;
        const float4 tr = *reinterpret_cast<const float4*>(traj + ((size_t)a * TT + t) * 4);
        float hx = tr.z, hy = tr.w;
        const float inv = rsqrtf(hx * hx + hy * hy);
        hx *= inv; hy *= inv;
        #pragma unroll
        for (int c = 0; c < NC; ++c) {
            const float cx = scc[c * NA + a];          // conflict-free LDS
            const float cy = scc[PLANE + c * NA + a];
            swx[c * NA + a] = fmaf(hx, cx, fmaf(-hy, cy, tr.x));
            swy[c * NA + a] = fmaf(hy, cx, fmaf( hx, cy, tr.y));
        }
    }
    __syncthreads();

    const int bi = c_bi[blockIdx.x];
    const int bj = c_bj[blockIdx.x];
    const int r  = tid >> 3;          // local i row 0..31
    const int q  = tid & 7;           // quad column 0..7
    const int i  = bi * 32 + r;
    const int j0 = bj * 32 + q * 4;

    // packed {-xi,-xi},{-yi,-yi} per circle (broadcast LDS)
    unsigned long long nxi[NC], nyi[NC];
    #pragma unroll
    for (int c = 0; c < NC; ++c) {
        PACK_NEG2(nxi[c], swx[c * NA + i]);
        PACK_NEG2(nyi[c], swy[c * NA + i]);
    }

    // scalar min accumulators split by c-parity: shorter RAW chains
    float m0a = 3.4e38f, m1a = 3.4e38f, m2a = 3.4e38f, m3a = 3.4e38f;
    float m0b = 3.4e38f, m1b = 3.4e38f, m2b = 3.4e38f, m3b = 3.4e38f;

    #pragma unroll
    for (int d = 0; d < NC; ++d) {
        const ulonglong2 xj = *reinterpret_cast<const ulonglong2*>(swx + d * NA + j0);
        const ulonglong2 yj = *reinterpret_cast<const ulonglong2*>(swy + d * NA + j0);
        #pragma unroll
        for (int c = 0; c < NC; ++c) {
            if (c & 1) {
                CIRC2(m0b, m1b, xj.x, nxi[c], yj.x, nyi[c]);
                CIRC2(m2b, m3b, xj.y, nxi[c], yj.y, nyi[c]);
            } else {
                CIRC2(m0a, m1a, xj.x, nxi[c], yj.x, nyi[c]);
                CIRC2(m2a, m3a, xj.y, nxi[c], yj.y, nyi[c]);
            }
        }
    }

    float mv[4];
    mv[0] = fminf(m0a, m0b);
    mv[1] = fminf(m1a, m1b);
    mv[2] = fminf(m2a, m2b);
    mv[3] = fminf(m3a, m3b);

    const int idx = i * NA + j0;
    const float4 p4 = *reinterpret_cast<const float4*>(pd + idx);
    const float pv[4] = {p4.x, p4.y, p4.z, p4.w};

    float4 pen, msk;
    float* penp = &pen.x;
    float* mskp = &msk.x;
    #pragma unroll
    for (int k = 0; k < 4; ++k) {
        const float m2e = mv[k] + 1e-30f;      // diagonal-zero guard for rsqrt
        float rr, ip;
        asm("rsqrt.approx.f32 %0, %1;" : "=f"(rr) : "f"(m2e));
        asm("rcp.approx.f32 %0, %1;"   : "=f"(ip) : "f"(pv[k]));
        const float mind = m2e * rr;           // = sqrt(m2e)
        penp[k] = fmaf(-mind, ip, 1.0f);
        // sqrt monotone: mind <= p  <=>  m2 <= p^2 ; diagonal excluded by i != j
        mskp[k] = (mv[k] <= pv[k] * pv[k] && i != j0 + k) ? 1.0f : 0.0f;
    }

    const size_t tbase = (size_t)t * (NA * NA);
    const size_t moff  = (size_t)TT * (NA * NA);

    // direct tile write
    *reinterpret_cast<float4*>(out + tbase + idx) = pen;
    *reinterpret_cast<float4*>(out + moff + tbase + idx) = msk;

    // mirrored tile write (off-diagonal tiles only; block-uniform branch)
    if (bi != bj) {
        #pragma unroll
        for (int k = 0; k < 4; ++k) {
            tpen[(q * 4 + k) * TP + r] = penp[k];
            tmsk[(q * 4 + k) * TP + r] = mskp[k];
        }
        __syncthreads();

        float4 vp, vm;
        float* vpp = &vp.x;
        float* vmp = &vm.x;
        #pragma unroll
        for (int k = 0; k < 4; ++k) {
            vpp[k] = tpen[r * TP + q * 4 + k];
            vmp[k] = tmsk[r * TP + q * 4 + k];
        }
        const int ot = (bj * 32 + r) * NA + bi * 32 + q * 4;
        *reinterpret_cast<float4*>(out + tbase + ot) = vp;
        *reinterpret_cast<float4*>(out + moff + tbase + ot) = vm;
    }
}

extern "C" void kernel_launch(void* const* d_in, const int* in_sizes, int n_in,
                              void* d_out, int out_size)
{
    const float* traj = (const float*)d_in[0];   // (192,80,4)
    const float* cent = (const float*)d_in[1];   // (192,5,4)
    const float* pd   = (const float*)d_in[2];   // (192,192)

    dim3 grid(NTILE, TT);   // (21, 80) — single launch
    veh_kernel<<<grid, THREADS>>>(traj, cent, pd, (float*)d_out);
}

// round 9
// speedup vs baseline: 1.1382x; 1.1382x over previous
#include <cuda_runtime.h>
#include <math.h>

#define NA 192
#define TT 80
#define NC 5
#define THREADS 256
#define NTILE 21            // upper-triangular 32x32 tiles of 192x192
#define TPB 3               // tiles per block
#define NBLK (NTILE / TPB)  // 7
#define PLANE (NC * NA)     // 960 floats per coordinate plane
#define TP 33               // transpose tile pitch (conflict-free)

__constant__ int c_bi[NTILE] = {0,0,0,0,0,0, 1,1,1,1,1, 2,2,2,2, 3,3,3, 4,4, 5};
__constant__ int c_bj[NTILE] = {0,1,2,3,4,5, 1,2,3,4,5, 2,3,4,5, 3,4,5, 4,5, 5};

// packed {-v, -v}
#define PACK_NEG2(dst, v) \
    asm("mov.b64 %0, {%1, %1};" : "=l"(dst) : "f"(-(v)))

// two squared distances (packed f32x2) + scalar running mins on the halves
#define CIRC2(mlo, mhi, xj, nxi, yj, nyi)                         \
    asm("{\n\t"                                                   \
        ".reg .b64 dx, dy, d2;\n\t"                               \
        ".reg .f32 lo, hi;\n\t"                                   \
        "add.rn.f32x2 dx, %2, %3;\n\t"                            \
        "add.rn.f32x2 dy, %4, %5;\n\t"                            \
        "mul.rn.f32x2 d2, dy, dy;\n\t"                            \
        "fma.rn.f32x2 d2, dx, dx, d2;\n\t"                        \
        "mov.b64 {lo, hi}, d2;\n\t"                               \
        "min.f32 %0, %0, lo;\n\t"                                 \
        "min.f32 %1, %1, hi;\n\t"                                 \
        "}"                                                       \
        : "+f"(mlo), "+f"(mhi)                                    \
        : "l"(xj), "l"(nxi), "l"(yj), "l"(nyi))

// ---- single fused kernel: build slab once, then 3 pair tiles ----
__global__ void __launch_bounds__(THREADS)
veh_kernel(const float* __restrict__ traj,   // (NA, T, 4)
           const float* __restrict__ cent,   // (NA, NC, 4)
           const float* __restrict__ pd,     // (NA, NA)
           float* __restrict__ out)
{
    const int t   = blockIdx.y;
    const int tid = threadIdx.x;

    __shared__ __align__(16) float s[2 * PLANE];     // world x then y (7.5 KB)
    __shared__ float tpen[32 * TP];
    __shared__ float tmsk[32 * TP];
    float* __restrict__ swx = s;
    float* __restrict__ swy = s + PLANE;

    // ---- build world circles for all 192 agents at this t ----
    if (tid < NA) {
        const int a = tid;
        const float4 tr = *reinterpret_cast<const float4*>(traj + ((size_t)a * TT + t) * 4);
        float hx = tr.z, hy = tr.w;
        const float inv = rsqrtf(hx * hx + hy * hy);
        hx *= inv; hy *= inv;
        #pragma unroll
        for (int c = 0; c < NC; ++c) {
            const float2 cc = *reinterpret_cast<const float2*>(cent + ((size_t)a * NC + c) * 4);
            swx[c * NA + a] = fmaf(hx, cc.x, fmaf(-hy, cc.y, tr.x));
            swy[c * NA + a] = fmaf(hy, cc.x, fmaf( hx, cc.y, tr.y));
        }
    }
    __syncthreads();

    const int r = tid >> 3;          // local i row 0..31
    const int q = tid & 7;           // quad column 0..7
    const size_t tbase = (size_t)t * (NA * NA);
    const size_t moff  = (size_t)TT * (NA * NA);

    #pragma unroll 1
    for (int it = 0; it < TPB; ++it) {
        const int tile = blockIdx.x * TPB + it;
        const int bi = c_bi[tile];
        const int bj = c_bj[tile];
        const int i  = bi * 32 + r;
        const int j0 = bj * 32 + q * 4;

        // packed {-xi,-xi},{-yi,-yi} per circle (broadcast LDS)
        unsigned long long nxi[NC], nyi[NC];
        #pragma unroll
        for (int c = 0; c < NC; ++c) {
            PACK_NEG2(nxi[c], swx[c * NA + i]);
            PACK_NEG2(nyi[c], swy[c * NA + i]);
        }

        // scalar min accumulators split by c-parity: shorter RAW chains
        float m0a = 3.4e38f, m1a = 3.4e38f, m2a = 3.4e38f, m3a = 3.4e38f;
        float m0b = 3.4e38f, m1b = 3.4e38f, m2b = 3.4e38f, m3b = 3.4e38f;

        #pragma unroll
        for (int d = 0; d < NC; ++d) {
            const ulonglong2 xj = *reinterpret_cast<const ulonglong2*>(swx + d * NA + j0);
            const ulonglong2 yj = *reinterpret_cast<const ulonglong2*>(swy + d * NA + j0);
            #pragma unroll
            for (int c = 0; c < NC; ++c) {
                if (c & 1) {
                    CIRC2(m0b, m1b, xj.x, nxi[c], yj.x, nyi[c]);
                    CIRC2(m2b, m3b, xj.y, nxi[c], yj.y, nyi[c]);
                } else {
                    CIRC2(m0a, m1a, xj.x, nxi[c], yj.x, nyi[c]);
                    CIRC2(m2a, m3a, xj.y, nxi[c], yj.y, nyi[c]);
                }
            }
        }

        float mv[4];
        mv[0] = fminf(m0a, m0b);
        mv[1] = fminf(m1a, m1b);
        mv[2] = fminf(m2a, m2b);
        mv[3] = fminf(m3a, m3b);

        const int idx = i * NA + j0;
        const float4 p4 = *reinterpret_cast<const float4*>(pd + idx);
        const float pv[4] = {p4.x, p4.y, p4.z, p4.w};

        float4 pen, msk;
        float* penp = &pen.x;
        float* mskp = &msk.x;
        #pragma unroll
        for (int k = 0; k < 4; ++k) {
            const float m2e = mv[k] + 1e-30f;      // diagonal-zero guard for rsqrt
            float rr, ip;
            asm("rsqrt.approx.f32 %0, %1;" : "=f"(rr) : "f"(m2e));
            asm("rcp.approx.f32 %0, %1;"   : "=f"(ip) : "f"(pv[k]));
            const float mind = m2e * rr;           // = sqrt(m2e)
            penp[k] = fmaf(-mind, ip, 1.0f);
            // sqrt monotone: mind <= p  <=>  m2 <= p^2 ; diagonal excluded by i != j
            mskp[k] = (mv[k] <= pv[k] * pv[k] && i != j0 + k) ? 1.0f : 0.0f;
        }

        // direct tile write
        *reinterpret_cast<float4*>(out + tbase + idx) = pen;
        *reinterpret_cast<float4*>(out + moff + tbase + idx) = msk;

        // mirrored tile write (off-diagonal tiles only; block-uniform branch)
        if (bi != bj) {
            __syncthreads();    // protect tpen/tmsk reuse across iterations
            #pragma unroll
            for (int k = 0; k < 4; ++k) {
                tpen[(q * 4 + k) * TP + r] = penp[k];
                tmsk[(q * 4 + k) * TP + r] = mskp[k];
            }
            __syncthreads();

            float4 vp, vm;
            float* vpp = &vp.x;
            float* vmp = &vm.x;
            #pragma unroll
            for (int k = 0; k < 4; ++k) {
                vpp[k] = tpen[r * TP + q * 4 + k];
                vmp[k] = tmsk[r * TP + q * 4 + k];
            }
            const int ot = (bj * 32 + r) * NA + bi * 32 + q * 4;
            *reinterpret_cast<float4*>(out + tbase + ot) = vp;
            *reinterpret_cast<float4*>(out + moff + tbase + ot) = vm;
        }
    }
}

extern "C" void kernel_launch(void* const* d_in, const int* in_sizes, int n_in,
                              void* d_out, int out_size)
{
    const float* traj = (const float*)d_in[0];   // (192,80,4)
    const float* cent = (const float*)d_in[1];   // (192,5,4)
    const float* pd   = (const float*)d_in[2];   // (192,192)

    dim3 grid(NBLK, TT);   // (7, 80) = 560 blocks — single wave, single launch
    veh_kernel<<<grid, THREADS>>>(traj, cent, pd, (float*)d_out);
}